// round 9
// baseline (speedup 1.0000x reference)
#include <cuda_runtime.h>
#include <cuda_fp16.h>
#include <cstdint>
#include <cstddef>

#define NMAX 50000
#define DIN 96
#define DOUT 256

// ---------------- scratch (__device__ globals; no allocs allowed) ----------
__device__ float  g_agg[(size_t)NMAX * DIN];
__device__ __half g_x16[(size_t)NMAX * DIN];        // fp16 copy of x
__device__ __half g_a16[(size_t)NMAX * DIN];        // fp16 agg [N][96]
__device__ __half g_h16[(size_t)NMAX * DOUT];       // fp16 h   [N][256]
__device__ __half g_b0ext[DOUT * (2 * DIN)];        // [256][192] = [W0h|W0l] (transposed)
__device__ __half g_b1ext[DOUT * (2 * DOUT)];       // [256][512] = [W1h|W1l] (transposed)

// ---------------- helpers ---------------------------------------------------
__device__ __forceinline__ uint32_t smem_u32(const void* p) {
    uint32_t a;
    asm("{ .reg .u64 t; cvta.to.shared.u64 t, %1; cvt.u32.u64 %0, t; }"
        : "=r"(a) : "l"(p));
    return a;
}
__device__ __forceinline__ void ldsm4(uint32_t* r, uint32_t addr) {
    asm volatile("ldmatrix.sync.aligned.m8n8.x4.shared.b16 {%0,%1,%2,%3}, [%4];"
                 : "=r"(r[0]), "=r"(r[1]), "=r"(r[2]), "=r"(r[3]) : "r"(addr));
}
__device__ __forceinline__ void mma16816(float* c, const uint32_t* a, const uint32_t* b) {
    asm volatile(
        "mma.sync.aligned.m16n8k16.row.col.f32.f16.f16.f32 "
        "{%0,%1,%2,%3}, {%4,%5,%6,%7}, {%8,%9}, {%0,%1,%2,%3};"
        : "+f"(c[0]), "+f"(c[1]), "+f"(c[2]), "+f"(c[3])
        : "r"(a[0]), "r"(a[1]), "r"(a[2]), "r"(a[3]), "r"(b[0]), "r"(b[1]));
}

// ---------------------------------------------------------------------------
// x fp32 -> fp16 copy (for the SpMM gather; halves L2 gather traffic)
// ---------------------------------------------------------------------------
__global__ void cvt_x_kernel(const float* __restrict__ x,
                             __half* __restrict__ x16, int n4) {
    int i = blockIdx.x * blockDim.x + threadIdx.x;
    if (i < n4) {
        float4 v = ((const float4*)x)[i];
        __half2 a = __floats2half2_rn(v.x, v.y);
        __half2 b = __floats2half2_rn(v.z, v.w);
        ((uint2*)x16)[i] = make_uint2(*(uint32_t*)&a, *(uint32_t*)&b);
    }
}

// ---------------------------------------------------------------------------
// agg = eps * x  (fp32 residual path, full precision)
// ---------------------------------------------------------------------------
__global__ void init_agg_kernel(const float* __restrict__ x,
                                const float* __restrict__ eps, int n4) {
    int i = blockIdx.x * blockDim.x + threadIdx.x;
    if (i < n4) {
        float e = eps[0];
        float4 v = ((const float4*)x)[i];
        v.x *= e; v.y *= e; v.z *= e; v.w *= e;
        ((float4*)g_agg)[i] = v;
    }
}

// ---------------------------------------------------------------------------
// agg[dst] += vals[e] * x16[src] via red.global.add.v4.f32
// 12 chunks/edge: each thread loads 8 halves (16B uint4), issues 2x red.v4.f32
// ---------------------------------------------------------------------------
__global__ void spmm_kernel(const __half* __restrict__ x16,
                            const int* __restrict__ src,
                            const int* __restrict__ dst,
                            const float* __restrict__ vals, int total) {
    int idx = blockIdx.x * blockDim.x + threadIdx.x;
    if (idx >= total) return;
    int e = idx / 12;
    int c = idx - e * 12;
    int s = src[e];
    int d = dst[e];
    float v = vals[e];
    uint4 pk = *(const uint4*)(x16 + (size_t)s * DIN + c * 8);
    const __half2* hp = (const __half2*)&pk;
    float2 f0 = __half22float2(hp[0]);
    float2 f1 = __half22float2(hp[1]);
    float2 f2 = __half22float2(hp[2]);
    float2 f3 = __half22float2(hp[3]);
    float* p = g_agg + (size_t)d * DIN + c * 8;
    asm volatile("red.global.add.v4.f32 [%0], {%1,%2,%3,%4};"
                 :: "l"(p), "f"(v * f0.x), "f"(v * f0.y),
                    "f"(v * f1.x), "f"(v * f1.y) : "memory");
    asm volatile("red.global.add.v4.f32 [%0], {%1,%2,%3,%4};"
                 :: "l"(p + 4), "f"(v * f2.x), "f"(v * f2.y),
                    "f"(v * f3.x), "f"(v * f3.y) : "memory");
}

// ---------------------------------------------------------------------------
// agg fp32 -> fp16 (elementwise, vectorized)
// ---------------------------------------------------------------------------
__global__ void cvt_agg_kernel(const float* __restrict__ src,
                               __half* __restrict__ dstp, int n4) {
    int i = blockIdx.x * blockDim.x + threadIdx.x;
    if (i < n4) {
        float4 v = ((const float4*)src)[i];
        __half2 a = __floats2half2_rn(v.x, v.y);
        __half2 b = __floats2half2_rn(v.z, v.w);
        ((uint2*)dstp)[i] = make_uint2(*(uint32_t*)&a, *(uint32_t*)&b);
    }
}

// ---------------------------------------------------------------------------
// Both weights: fp32 W[K][256] -> Bext fp16 [256][2K] = [Wh|Wl] transposed
// ---------------------------------------------------------------------------
__global__ void wsplit_kernel(const float* __restrict__ W0,
                              const float* __restrict__ W1,
                              __half* __restrict__ B0,
                              __half* __restrict__ B1) {
    int i = blockIdx.x * blockDim.x + threadIdx.x;
    const int n0 = DIN * DOUT;
    if (i < n0) {
        int k = i / DOUT, n = i - k * DOUT;
        float v = W0[i];
        __half h = __float2half_rn(v);
        size_t base = (size_t)n * (2 * DIN);
        B0[base + k] = h;
        B0[base + DIN + k] = __float2half_rn(v - __half2float(h));
    } else if (i < n0 + DOUT * DOUT) {
        int j = i - n0;
        int k = j / DOUT, n = j - k * DOUT;
        float v = W1[j];
        __half h = __float2half_rn(v);
        size_t base = (size_t)n * (2 * DOUT);
        B1[base + k] = h;
        B1[base + DOUT + k] = __float2half_rn(v - __half2float(h));
    }
}

// ---------------------------------------------------------------------------
// fp16 HMMA GEMM, extended K (weight hi/lo in K), 3-stage cp.async pipeline.
// ---------------------------------------------------------------------------
#define STG_BYTES (128 * 80)
#define NSTAGE 3
#define OFF_B (NSTAGE * STG_BYTES)
#define OFF_SC (2 * NSTAGE * STG_BYTES)
#define OFF_BI (OFF_SC + 512)
#define GEMM_SMEM (OFF_BI + 512)

template <int MODE, int KP, int WRAP>
__global__ void __launch_bounds__(256)
gemm_mma(const __half* __restrict__ Aext,
         const __half* __restrict__ Bext,
         float* __restrict__ Cf, __half* __restrict__ Ch, int M,
         const float* __restrict__ gamma, const float* __restrict__ beta,
         const float* __restrict__ mean, const float* __restrict__ var) {
    extern __shared__ __align__(16) unsigned char smem[];

    const int tid = threadIdx.x;
    const int wid = tid >> 5, lane = tid & 31;
    const int mBlock = blockIdx.y * 128, nBlock = blockIdx.x * 128;
    const int wm = wid & 3, wn = wid >> 2;
    const int tq = lane >> 2, tr = lane & 3;

    const uint32_t aBase = smem_u32(smem);
    const uint32_t bBase = aBase + OFF_B;
    float* s_sc = (float*)(smem + OFF_SC);
    float* s_bi = (float*)(smem + OFF_BI);

    const int ldrow = tid >> 2;
    const int ldkc = tid & 3;

    const int arow = ((lane >> 3) & 1) * 8 + (lane & 7);
    const int akb = (lane >> 4) * 8;
    const int brow = ((lane >> 4) & 1) * 8 + (lane & 7);
    const int bkb = ((lane >> 3) & 1) * 8;
    const uint32_t aAddr0 = aBase + (uint32_t)(wm * 32 + arow) * 80 + akb * 2;
    const uint32_t bAddr0 = bBase + (uint32_t)(wn * 64 + brow) * 80 + bkb * 2;

    float acc[2][8][4];
#pragma unroll
    for (int i = 0; i < 2; i++)
#pragma unroll
        for (int j = 0; j < 8; j++)
#pragma unroll
            for (int q = 0; q < 4; q++) acc[i][j][q] = 0.f;

    constexpr int NS = KP / 32;

    auto issue = [&](int ks, int stage) {
        const int k0 = ks * 32;
        const int ksA = (k0 >= WRAP) ? k0 - WRAP : k0;
#pragma unroll
        for (int i = 0; i < 2; i++) {
            int row = ldrow + i * 64;
            uint32_t sa = aBase + stage * STG_BYTES + row * 80 + ldkc * 16;
            const void* ga = Aext + (size_t)(mBlock + row) * WRAP + ksA + ldkc * 8;
            int sz = (mBlock + row < M) ? 16 : 0;
            asm volatile("cp.async.cg.shared.global [%0], [%1], 16, %2;"
                         :: "r"(sa), "l"(ga), "r"(sz) : "memory");
            uint32_t sb = bBase + stage * STG_BYTES + row * 80 + ldkc * 16;
            const void* gb = Bext + (size_t)(nBlock + row) * KP + k0 + ldkc * 8;
            asm volatile("cp.async.cg.shared.global [%0], [%1], 16;"
                         :: "r"(sb), "l"(gb) : "memory");
        }
        asm volatile("cp.async.commit_group;" ::: "memory");
    };

    issue(0, 0);
    if (NS > 1) issue(1, 1);

    for (int ks = 0; ks < NS; ks++) {
        if (ks + 1 < NS) {
            asm volatile("cp.async.wait_group 1;" ::: "memory");
        } else {
            asm volatile("cp.async.wait_group 0;" ::: "memory");
        }
        __syncthreads();
        if (ks + NSTAGE - 1 < NS)
            issue(ks + NSTAGE - 1, (ks + NSTAGE - 1) % NSTAGE);

        const int st = ks % NSTAGE;
        const uint32_t aS = aAddr0 + st * STG_BYTES;
        const uint32_t bS = bAddr0 + st * STG_BYTES;
#pragma unroll
        for (int ksub = 0; ksub < 2; ksub++) {
            uint32_t a[2][4];
#pragma unroll
            for (int mt = 0; mt < 2; mt++)
                ldsm4(a[mt], aS + mt * (16 * 80) + ksub * 32);
            uint32_t b[8][2];
#pragma unroll
            for (int np = 0; np < 4; np++) {
                uint32_t t[4];
                ldsm4(t, bS + np * (16 * 80) + ksub * 32);
                b[2 * np][0] = t[0]; b[2 * np][1] = t[1];
                b[2 * np + 1][0] = t[2]; b[2 * np + 1][1] = t[3];
            }
#pragma unroll
            for (int mt = 0; mt < 2; mt++)
#pragma unroll
                for (int nt = 0; nt < 8; nt++)
                    mma16816(acc[mt][nt], a[mt], b[nt]);
        }
    }
    __syncthreads();

    if (MODE == 0) {
        if (tid < 128) {
            int col = nBlock + tid;
            float s = gamma[col] * rsqrtf(var[col] + 1e-3f);
            s_sc[tid] = s;
            s_bi[tid] = beta[col] - mean[col] * s;
        }
        __syncthreads();
    }

#pragma unroll
    for (int mt = 0; mt < 2; mt++) {
        const int m0 = mBlock + wm * 32 + mt * 16 + tq;
#pragma unroll
        for (int nt = 0; nt < 8; nt++) {
            const int cloc = wn * 64 + nt * 8 + 2 * tr;
            const int col = nBlock + cloc;
            float* c = acc[mt][nt];
            if (MODE == 0) {
                float s0 = s_sc[cloc], s1 = s_sc[cloc + 1];
                float b0 = s_bi[cloc], b1 = s_bi[cloc + 1];
                if (m0 < M) {
                    float v0 = fmaxf(fmaf(c[0], s0, b0), 0.f);
                    float v1 = fmaxf(fmaf(c[1], s1, b1), 0.f);
                    __half2 p = __floats2half2_rn(v0, v1);
                    *(__half2*)(Ch + (size_t)m0 * DOUT + col) = p;
                }
                if (m0 + 8 < M) {
                    float v0 = fmaxf(fmaf(c[2], s0, b0), 0.f);
                    float v1 = fmaxf(fmaf(c[3], s1, b1), 0.f);
                    __half2 p = __floats2half2_rn(v0, v1);
                    *(__half2*)(Ch + (size_t)(m0 + 8) * DOUT + col) = p;
                }
            } else {
                if (m0 < M)
                    *(float2*)(Cf + (size_t)m0 * DOUT + col) =
                        make_float2(c[0], c[1]);
                if (m0 + 8 < M)
                    *(float2*)(Cf + (size_t)(m0 + 8) * DOUT + col) =
                        make_float2(c[2], c[3]);
            }
        }
    }
}

// ---------------------------------------------------------------------------
extern "C" void kernel_launch(void* const* d_in, const int* in_sizes, int n_in,
                              void* d_out, int out_size) {
    const float* x     = (const float*)d_in[0];
    const int*   src   = (const int*)d_in[1];
    const int*   dst   = (const int*)d_in[2];
    const float* vals  = (const float*)d_in[3];
    const float* eps   = (const float*)d_in[4];
    const float* W0    = (const float*)d_in[5];
    const float* W1    = (const float*)d_in[6];
    const float* gamma = (const float*)d_in[7];
    const float* beta  = (const float*)d_in[8];
    const float* mean  = (const float*)d_in[9];
    const float* var   = (const float*)d_in[10];

    int N = in_sizes[0] / DIN;
    int E = in_sizes[1];

    float* agg;            cudaGetSymbolAddress((void**)&agg, g_agg);
    __half *x16, *a16, *h16, *b0ext, *b1ext;
    cudaGetSymbolAddress((void**)&x16, g_x16);
    cudaGetSymbolAddress((void**)&a16, g_a16);
    cudaGetSymbolAddress((void**)&h16, g_h16);
    cudaGetSymbolAddress((void**)&b0ext, g_b0ext);
    cudaGetSymbolAddress((void**)&b1ext, g_b1ext);

    cudaFuncSetAttribute(gemm_mma<0, 2 * DIN, DIN>,
                         cudaFuncAttributeMaxDynamicSharedMemorySize, GEMM_SMEM);
    cudaFuncSetAttribute(gemm_mma<1, 2 * DOUT, DOUT>,
                         cudaFuncAttributeMaxDynamicSharedMemorySize, GEMM_SMEM);

    // weight transpose + hi/lo split (one small launch)
    int wtot = DIN * DOUT + DOUT * DOUT;
    wsplit_kernel<<<(wtot + 255) / 256, 256>>>(W0, W1, b0ext, b1ext);

    int n4 = N * (DIN / 4);
    // 0. x -> fp16 copy for the gather
    cvt_x_kernel<<<(n4 + 255) / 256, 256>>>(x, x16, n4);

    // 1. agg = eps * x  (fp32)
    init_agg_kernel<<<(n4 + 255) / 256, 256>>>(x, eps, n4);

    // 2. scatter-add edge messages (fp16 gather, fp32 atomics)
    int total = E * (DIN / 8);
    spmm_kernel<<<(total + 255) / 256, 256>>>(x16, src, dst, vals, total);

    // 3. agg -> fp16
    cvt_agg_kernel<<<(n4 + 255) / 256, 256>>>(agg, a16, n4);

    // 4. h = relu(bn(agg @ W0))   (K' = 192, wrap 96)
    dim3 grid(DOUT / 128, (N + 127) / 128);
    gemm_mma<0, 2 * DIN, DIN><<<grid, 256, GEMM_SMEM>>>(
        a16, b0ext, nullptr, h16, N, gamma, beta, mean, var);

    // 5. out = h @ W1             (K' = 512, wrap 256)
    gemm_mma<1, 2 * DOUT, DOUT><<<grid, 256, GEMM_SMEM>>>(
        h16, b1ext, (float*)d_out, nullptr, N,
        nullptr, nullptr, nullptr, nullptr);
}

// round 10
// speedup vs baseline: 1.2455x; 1.2455x over previous
#include <cuda_runtime.h>
#include <cuda_fp16.h>
#include <cstdint>
#include <cstddef>

#define NMAX 50000
#define DIN 96
#define DOUT 256

// ---------------- scratch (__device__ globals; no allocs allowed) ----------
__device__ float  g_agg[(size_t)NMAX * DIN];
__device__ __half g_a16[(size_t)NMAX * DIN];        // fp16 agg [N][96]
__device__ __half g_h16[(size_t)NMAX * DOUT];       // fp16 h   [N][256]
__device__ __half g_b0ext[DOUT * (2 * DIN)];        // [256][192] = [W0h|W0l] (transposed)
__device__ __half g_b1t[DOUT * DOUT];               // [256][256] = W1^T (single fp16)

// ---------------- helpers ---------------------------------------------------
__device__ __forceinline__ uint32_t smem_u32(const void* p) {
    uint32_t a;
    asm("{ .reg .u64 t; cvta.to.shared.u64 t, %1; cvt.u32.u64 %0, t; }"
        : "=r"(a) : "l"(p));
    return a;
}
__device__ __forceinline__ void ldsm4(uint32_t* r, uint32_t addr) {
    asm volatile("ldmatrix.sync.aligned.m8n8.x4.shared.b16 {%0,%1,%2,%3}, [%4];"
                 : "=r"(r[0]), "=r"(r[1]), "=r"(r[2]), "=r"(r[3]) : "r"(addr));
}
__device__ __forceinline__ void mma16816(float* c, const uint32_t* a, const uint32_t* b) {
    asm volatile(
        "mma.sync.aligned.m16n8k16.row.col.f32.f16.f16.f32 "
        "{%0,%1,%2,%3}, {%4,%5,%6,%7}, {%8,%9}, {%0,%1,%2,%3};"
        : "+f"(c[0]), "+f"(c[1]), "+f"(c[2]), "+f"(c[3])
        : "r"(a[0]), "r"(a[1]), "r"(a[2]), "r"(a[3]), "r"(b[0]), "r"(b[1]));
}

// ---------------------------------------------------------------------------
// agg = eps * x  (fp32 residual path, full precision)
// ---------------------------------------------------------------------------
__global__ void init_agg_kernel(const float* __restrict__ x,
                                const float* __restrict__ eps, int n4) {
    int i = blockIdx.x * blockDim.x + threadIdx.x;
    if (i < n4) {
        float e = eps[0];
        float4 v = ((const float4*)x)[i];
        v.x *= e; v.y *= e; v.z *= e; v.w *= e;
        ((float4*)g_agg)[i] = v;
    }
}

// ---------------------------------------------------------------------------
// agg[dst] += vals[e] * x[src] via red.global.add.v4.f32  (fp32 gather)
// ---------------------------------------------------------------------------
__global__ void spmm_kernel(const float* __restrict__ x,
                            const int* __restrict__ src,
                            const int* __restrict__ dst,
                            const float* __restrict__ vals, int total) {
    int idx = blockIdx.x * blockDim.x + threadIdx.x;
    if (idx >= total) return;
    int e = idx / 24;
    int c = idx - e * 24;
    int s = src[e];
    int d = dst[e];
    float v = vals[e];
    float4 xv = *(const float4*)(x + (size_t)s * DIN + c * 4);
    float* p = g_agg + (size_t)d * DIN + c * 4;
    asm volatile("red.global.add.v4.f32 [%0], {%1,%2,%3,%4};"
                 :: "l"(p), "f"(v * xv.x), "f"(v * xv.y),
                    "f"(v * xv.z), "f"(v * xv.w) : "memory");
}

// ---------------------------------------------------------------------------
// agg fp32 -> fp16 (elementwise, vectorized)
// ---------------------------------------------------------------------------
__global__ void cvt_agg_kernel(const float* __restrict__ src,
                               __half* __restrict__ dstp, int n4) {
    int i = blockIdx.x * blockDim.x + threadIdx.x;
    if (i < n4) {
        float4 v = ((const float4*)src)[i];
        __half2 a = __floats2half2_rn(v.x, v.y);
        __half2 b = __floats2half2_rn(v.z, v.w);
        ((uint2*)dstp)[i] = make_uint2(*(uint32_t*)&a, *(uint32_t*)&b);
    }
}

// ---------------------------------------------------------------------------
// W0 fp32 [96][256] -> B0 fp16 [256][192] = [W0h|W0l] transposed (split)
// W1 fp32 [256][256] -> B1 fp16 [256][256] transposed (single)
// ---------------------------------------------------------------------------
__global__ void wprep_kernel(const float* __restrict__ W0,
                             const float* __restrict__ W1,
                             __half* __restrict__ B0,
                             __half* __restrict__ B1) {
    int i = blockIdx.x * blockDim.x + threadIdx.x;
    const int n0 = DIN * DOUT;
    if (i < n0) {
        int k = i / DOUT, n = i - k * DOUT;
        float v = W0[i];
        __half h = __float2half_rn(v);
        size_t base = (size_t)n * (2 * DIN);
        B0[base + k] = h;
        B0[base + DIN + k] = __float2half_rn(v - __half2float(h));
    } else if (i < n0 + DOUT * DOUT) {
        int j = i - n0;
        int k = j / DOUT, n = j - k * DOUT;
        B1[(size_t)n * DOUT + k] = __float2half_rn(W1[j]);
    }
}

// ---------------------------------------------------------------------------
// fp16 HMMA GEMM, 3-stage cp.async pipeline, optional K-wrap for A
// (wrap encodes the weight-hi/lo K-extension; WRAP==KP means no wrap).
//   C[M,256] tile 128x128, 8 warps (4x2), warp tile 32x64, mma m16n8k16.
//   MODE 0: BN+ReLU epilogue, write fp16 Ch [M][256]
//   MODE 1: plain epilogue, write fp32 Cf [M][256]
// ---------------------------------------------------------------------------
#define STG_BYTES (128 * 80)
#define NSTAGE 3
#define OFF_B (NSTAGE * STG_BYTES)
#define OFF_SC (2 * NSTAGE * STG_BYTES)
#define OFF_BI (OFF_SC + 512)
#define GEMM_SMEM (OFF_BI + 512)

template <int MODE, int KP, int WRAP>
__global__ void __launch_bounds__(256)
gemm_mma(const __half* __restrict__ Aext,
         const __half* __restrict__ Bext,
         float* __restrict__ Cf, __half* __restrict__ Ch, int M,
         const float* __restrict__ gamma, const float* __restrict__ beta,
         const float* __restrict__ mean, const float* __restrict__ var) {
    extern __shared__ __align__(16) unsigned char smem[];

    const int tid = threadIdx.x;
    const int wid = tid >> 5, lane = tid & 31;
    const int mBlock = blockIdx.y * 128, nBlock = blockIdx.x * 128;
    const int wm = wid & 3, wn = wid >> 2;
    const int tq = lane >> 2, tr = lane & 3;

    const uint32_t aBase = smem_u32(smem);
    const uint32_t bBase = aBase + OFF_B;
    float* s_sc = (float*)(smem + OFF_SC);
    float* s_bi = (float*)(smem + OFF_BI);

    const int ldrow = tid >> 2;
    const int ldkc = tid & 3;

    const int arow = ((lane >> 3) & 1) * 8 + (lane & 7);
    const int akb = (lane >> 4) * 8;
    const int brow = ((lane >> 4) & 1) * 8 + (lane & 7);
    const int bkb = ((lane >> 3) & 1) * 8;
    const uint32_t aAddr0 = aBase + (uint32_t)(wm * 32 + arow) * 80 + akb * 2;
    const uint32_t bAddr0 = bBase + (uint32_t)(wn * 64 + brow) * 80 + bkb * 2;

    float acc[2][8][4];
#pragma unroll
    for (int i = 0; i < 2; i++)
#pragma unroll
        for (int j = 0; j < 8; j++)
#pragma unroll
            for (int q = 0; q < 4; q++) acc[i][j][q] = 0.f;

    constexpr int NS = KP / 32;

    auto issue = [&](int ks, int stage) {
        const int k0 = ks * 32;
        const int ksA = (k0 >= WRAP) ? k0 - WRAP : k0;
#pragma unroll
        for (int i = 0; i < 2; i++) {
            int row = ldrow + i * 64;
            uint32_t sa = aBase + stage * STG_BYTES + row * 80 + ldkc * 16;
            const void* ga = Aext + (size_t)(mBlock + row) * WRAP + ksA + ldkc * 8;
            int sz = (mBlock + row < M) ? 16 : 0;
            asm volatile("cp.async.cg.shared.global [%0], [%1], 16, %2;"
                         :: "r"(sa), "l"(ga), "r"(sz) : "memory");
            uint32_t sb = bBase + stage * STG_BYTES + row * 80 + ldkc * 16;
            const void* gb = Bext + (size_t)(nBlock + row) * KP + k0 + ldkc * 8;
            asm volatile("cp.async.cg.shared.global [%0], [%1], 16;"
                         :: "r"(sb), "l"(gb) : "memory");
        }
        asm volatile("cp.async.commit_group;" ::: "memory");
    };

    issue(0, 0);
    if (NS > 1) issue(1, 1);

    for (int ks = 0; ks < NS; ks++) {
        if (ks + 1 < NS) {
            asm volatile("cp.async.wait_group 1;" ::: "memory");
        } else {
            asm volatile("cp.async.wait_group 0;" ::: "memory");
        }
        __syncthreads();
        if (ks + NSTAGE - 1 < NS)
            issue(ks + NSTAGE - 1, (ks + NSTAGE - 1) % NSTAGE);

        const int st = ks % NSTAGE;
        const uint32_t aS = aAddr0 + st * STG_BYTES;
        const uint32_t bS = bAddr0 + st * STG_BYTES;
#pragma unroll
        for (int ksub = 0; ksub < 2; ksub++) {
            uint32_t a[2][4];
#pragma unroll
            for (int mt = 0; mt < 2; mt++)
                ldsm4(a[mt], aS + mt * (16 * 80) + ksub * 32);
            uint32_t b[8][2];
#pragma unroll
            for (int np = 0; np < 4; np++) {
                uint32_t t[4];
                ldsm4(t, bS + np * (16 * 80) + ksub * 32);
                b[2 * np][0] = t[0]; b[2 * np][1] = t[1];
                b[2 * np + 1][0] = t[2]; b[2 * np + 1][1] = t[3];
            }
#pragma unroll
            for (int mt = 0; mt < 2; mt++)
#pragma unroll
                for (int nt = 0; nt < 8; nt++)
                    mma16816(acc[mt][nt], a[mt], b[nt]);
        }
    }
    __syncthreads();

    if (MODE == 0) {
        if (tid < 128) {
            int col = nBlock + tid;
            float s = gamma[col] * rsqrtf(var[col] + 1e-3f);
            s_sc[tid] = s;
            s_bi[tid] = beta[col] - mean[col] * s;
        }
        __syncthreads();
    }

#pragma unroll
    for (int mt = 0; mt < 2; mt++) {
        const int m0 = mBlock + wm * 32 + mt * 16 + tq;
#pragma unroll
        for (int nt = 0; nt < 8; nt++) {
            const int cloc = wn * 64 + nt * 8 + 2 * tr;
            const int col = nBlock + cloc;
            float* c = acc[mt][nt];
            if (MODE == 0) {
                float s0 = s_sc[cloc], s1 = s_sc[cloc + 1];
                float b0 = s_bi[cloc], b1 = s_bi[cloc + 1];
                if (m0 < M) {
                    float v0 = fmaxf(fmaf(c[0], s0, b0), 0.f);
                    float v1 = fmaxf(fmaf(c[1], s1, b1), 0.f);
                    __half2 p = __floats2half2_rn(v0, v1);
                    *(__half2*)(Ch + (size_t)m0 * DOUT + col) = p;
                }
                if (m0 + 8 < M) {
                    float v0 = fmaxf(fmaf(c[2], s0, b0), 0.f);
                    float v1 = fmaxf(fmaf(c[3], s1, b1), 0.f);
                    __half2 p = __floats2half2_rn(v0, v1);
                    *(__half2*)(Ch + (size_t)(m0 + 8) * DOUT + col) = p;
                }
            } else {
                if (m0 < M)
                    *(float2*)(Cf + (size_t)m0 * DOUT + col) =
                        make_float2(c[0], c[1]);
                if (m0 + 8 < M)
                    *(float2*)(Cf + (size_t)(m0 + 8) * DOUT + col) =
                        make_float2(c[2], c[3]);
            }
        }
    }
}

// ---------------------------------------------------------------------------
extern "C" void kernel_launch(void* const* d_in, const int* in_sizes, int n_in,
                              void* d_out, int out_size) {
    const float* x     = (const float*)d_in[0];
    const int*   src   = (const int*)d_in[1];
    const int*   dst   = (const int*)d_in[2];
    const float* vals  = (const float*)d_in[3];
    const float* eps   = (const float*)d_in[4];
    const float* W0    = (const float*)d_in[5];
    const float* W1    = (const float*)d_in[6];
    const float* gamma = (const float*)d_in[7];
    const float* beta  = (const float*)d_in[8];
    const float* mean  = (const float*)d_in[9];
    const float* var   = (const float*)d_in[10];

    int N = in_sizes[0] / DIN;
    int E = in_sizes[1];

    float* agg;            cudaGetSymbolAddress((void**)&agg, g_agg);
    __half *a16, *h16, *b0ext, *b1t;
    cudaGetSymbolAddress((void**)&a16, g_a16);
    cudaGetSymbolAddress((void**)&h16, g_h16);
    cudaGetSymbolAddress((void**)&b0ext, g_b0ext);
    cudaGetSymbolAddress((void**)&b1t, g_b1t);

    cudaFuncSetAttribute(gemm_mma<0, 2 * DIN, DIN>,
                         cudaFuncAttributeMaxDynamicSharedMemorySize, GEMM_SMEM);
    cudaFuncSetAttribute(gemm_mma<1, DOUT, DOUT>,
                         cudaFuncAttributeMaxDynamicSharedMemorySize, GEMM_SMEM);

    // weight prep: W0 split, W1 plain transpose
    int wtot = DIN * DOUT + DOUT * DOUT;
    wprep_kernel<<<(wtot + 255) / 256, 256>>>(W0, W1, b0ext, b1t);

    int n4 = N * (DIN / 4);
    // 1. agg = eps * x  (fp32)
    init_agg_kernel<<<(n4 + 255) / 256, 256>>>(x, eps, n4);

    // 2. scatter-add edge messages (fp32 gather + fp32 atomics)
    int total = E * (DIN / 4);
    spmm_kernel<<<(total + 255) / 256, 256>>>(x, src, dst, vals, total);

    // 3. agg -> fp16
    cvt_agg_kernel<<<(n4 + 255) / 256, 256>>>(agg, a16, n4);

    // 4. h = relu(bn(agg @ W0))   (K' = 192, wrap 96: W0 hi/lo split)
    dim3 grid(DOUT / 128, (N + 127) / 128);
    gemm_mma<0, 2 * DIN, DIN><<<grid, 256, GEMM_SMEM>>>(
        a16, b0ext, nullptr, h16, N, gamma, beta, mean, var);

    // 5. out = h @ W1             (K = 256, no split)
    gemm_mma<1, DOUT, DOUT><<<grid, 256, GEMM_SMEM>>>(
        h16, b1t, (float*)d_out, nullptr, N,
        nullptr, nullptr, nullptr, nullptr);
}